// round 15
// baseline (speedup 1.0000x reference)
#include <cuda_runtime.h>
#include <cuda_fp16.h>
#include <cstddef>
#include <cstdint>

#define NN 4096
#define FF 256
#define KK 8
#define FP 64
#define KF 512   // KK*FP

#define BKA 32
#define NTA (NN / BKA)        // 128 m-tiles total
#define TMA 64                // n-rows per CTA
#define SPLIT 4
#define MSPL (NN / SPLIT)     // 1024 m per split
#define TPS (MSPL / BKA)      // 32 tiles per CTA

typedef unsigned int u32;

// ---------------- scratch (static device globals; no allocation) ----------------
__device__ float  g_xe[NN * KF];              // 8 MB xe[n][k*64+f]
__device__ __half g_xeT[KK * NTA * FP * BKA]; // 4 MB tiled: [k][mtile][f][32]
__device__ float  g_hl[KK * NN];
__device__ float  g_hr[KK * NN];
__device__ u32    g_mbits[NTA * NN];          // 2 MB bit-packed mask, TRANSPOSED [mw][n]
__device__ float  g_po[SPLIT * NN * KF];      // 32 MB partial O
__device__ float  g_ps[SPLIT * KK * NN];      // partial row sums
__device__ int    g_code;                     // 0=u8/bool, 1=int32, 2=float32

// ---------------- mask accessor ----------------
__device__ __forceinline__ unsigned mask_at(const void* m, int code, size_t idx) {
    if (code == 0)      return (unsigned)((const unsigned char*)m)[idx];
    else if (code == 1) return ((const int*)m)[idx] != 0;
    else                return __float_as_uint(((const float*)m)[idx]) != 0u;
}

// per-block dtype detection on first 4 KB (deterministic; all blocks agree)
__device__ __forceinline__ int detect_code_block(const void* mask) {
    __shared__ u32 sh0, sh1;
    if (threadIdx.x == 0) { sh0 = 0u; sh1 = 0u; }
    __syncthreads();
    const u32* wp = (const u32*)mask;
    u32 o0 = 0u, o1 = 0u;
    for (int i = threadIdx.x; i < 1024; i += blockDim.x) {
        u32 v = wp[i];
        o0 |= (v & 0xFFu);
        o1 |= ((v >> 8) & 0xFFu);
    }
    atomicOr(&sh0, o0);
    atomicOr(&sh1, o1);
    __syncthreads();
    return sh1 ? 0 : (sh0 ? 1 : 2);
}

__device__ __forceinline__ u32 smem_u32(const void* p) {
    u32 a;
    asm("{ .reg .u64 t; cvta.to.shared.u64 t, %1; cvt.u32.u64 %0, t; }"
        : "=r"(a) : "l"(p));
    return a;
}

__device__ __forceinline__ void ldsm_x4(u32& r0, u32& r1, u32& r2, u32& r3, u32 a) {
    asm volatile("ldmatrix.sync.aligned.m8n8.x4.shared.b16 {%0,%1,%2,%3}, [%4];"
                 : "=r"(r0), "=r"(r1), "=r"(r2), "=r"(r3) : "r"(a));
}

#define HMMA(ac, a0, a1, a2, a3, bb0, bb1)                                     \
    asm("mma.sync.aligned.m16n8k16.row.col.f32.f16.f16.f32 "                   \
        "{%0,%1,%2,%3}, {%4,%5,%6,%7}, {%8,%9}, {%0,%1,%2,%3};"                \
        : "+f"((ac)[0]), "+f"((ac)[1]), "+f"((ac)[2]), "+f"((ac)[3])           \
        : "r"(a0), "r"(a1), "r"(a2), "r"(a3), "r"(bb0), "r"(bb1))

// ---------------- K1: bit-pack mask, TRANSPOSED [mw][n] ----------------
__global__ void __launch_bounds__(256) k_bitpack(const void* __restrict__ mask) {
    int code = detect_code_block(mask);
    if (blockIdx.x == 0 && threadIdx.x == 0) g_code = code;
    int idx = blockIdx.x * blockDim.x + threadIdx.x;   // 0 .. NN*128-1
    int n = idx >> 7, mw = idx & 127;
    u32 bits = 0u;
    if (code == 0) {
        const u32* wp = (const u32*)mask + (size_t)idx * 8;
#pragma unroll
        for (int i = 0; i < 8; i++) {
            u32 v = wp[i];
            bits |= ((v & 1u) << (4 * i)) | (((v >> 8) & 1u) << (4 * i + 1)) |
                    (((v >> 16) & 1u) << (4 * i + 2)) | (((v >> 24) & 1u) << (4 * i + 3));
        }
    } else {
        size_t base = (size_t)idx * 32;
        for (int j = 0; j < 32; j++)
            bits |= mask_at(mask, code, base + j) << j;
    }
    g_mbits[(size_t)mw * NN + n] = bits;
}

// ---------------- K2: xe = x @ W^T + b, fused hl/hr ----------------
__global__ void __launch_bounds__(256) gemm_xe(const float* __restrict__ x,
                                               const float* __restrict__ W,
                                               const float* __restrict__ b,
                                               const float* __restrict__ aL,
                                               const float* __restrict__ aR) {
    __shared__ float sA[16][68];
    __shared__ float sB[16][68];
    int tid = threadIdx.x;
    int tx = tid & 15, ty = tid >> 4;
    int row0 = blockIdx.y * 64;
    int head = blockIdx.x;
    int col0 = head * 64;
    float acc[4][4];
#pragma unroll
    for (int i = 0; i < 4; i++)
#pragma unroll
        for (int j = 0; j < 4; j++) acc[i][j] = 0.f;

    for (int t = 0; t < FF / 16; t++) {
#pragma unroll
        for (int l = 0; l < 4; l++) {
            int idx = tid + l * 256;
            int mm = idx >> 4, kk = idx & 15;
            sA[kk][mm] = x[(size_t)(row0 + mm) * FF + t * 16 + kk];
            sB[kk][mm] = W[(size_t)(col0 + mm) * FF + t * 16 + kk];
        }
        __syncthreads();
#pragma unroll
        for (int kk = 0; kk < 16; kk++) {
            float a[4], bv[4];
#pragma unroll
            for (int i = 0; i < 4; i++) a[i] = sA[kk][ty * 4 + i];
#pragma unroll
            for (int j = 0; j < 4; j++) bv[j] = sB[kk][tx * 4 + j];
#pragma unroll
            for (int i = 0; i < 4; i++)
#pragma unroll
                for (int j = 0; j < 4; j++) acc[i][j] += a[i] * bv[j];
        }
        __syncthreads();
    }

    float hlv[4] = {0.f, 0.f, 0.f, 0.f}, hrv[4] = {0.f, 0.f, 0.f, 0.f};
#pragma unroll
    for (int j = 0; j < 4; j++) {
        int c = col0 + tx * 4 + j;
        float aLj = aL[head * FP + tx * 4 + j];
        float aRj = aR[head * FP + tx * 4 + j];
        float bj = b[c];
#pragma unroll
        for (int i = 0; i < 4; i++) {
            float v = acc[i][j] + bj;
            hlv[i] += v * aLj;
            hrv[i] += v * aRj;
            g_xe[(size_t)(row0 + ty * 4 + i) * KF + c] = v;
        }
    }
#pragma unroll
    for (int i = 0; i < 4; i++) {
#pragma unroll
        for (int off = 8; off; off >>= 1) {
            hlv[i] += __shfl_xor_sync(0xffffffffu, hlv[i], off);
            hrv[i] += __shfl_xor_sync(0xffffffffu, hrv[i], off);
        }
    }
    if (tx == 0) {
#pragma unroll
        for (int i = 0; i < 4; i++) {
            int n = row0 + ty * 4 + i;
            g_hl[head * NN + n] = hlv[i];
            g_hr[head * NN + n] = hrv[i];
        }
    }
}

// ---------------- K3: xe -> TILED fp16 xeT[k][mtile][f][32] ------------------
__global__ void __launch_bounds__(128) k_xt() {
    __shared__ float tile[32][65];
    int tid = threadIdx.x;
    int mt = blockIdx.x, head = blockIdx.y;

    int r = tid >> 2, c = (tid & 3) * 16;
    const float* src = &g_xe[(size_t)(mt * 32 + r) * KF + head * FP + c];
#pragma unroll
    for (int i = 0; i < 4; i++) {
        float4 v = *(const float4*)(src + i * 4);
        tile[r][c + i * 4 + 0] = v.x;
        tile[r][c + i * 4 + 1] = v.y;
        tile[r][c + i * 4 + 2] = v.z;
        tile[r][c + i * 4 + 3] = v.w;
    }
    __syncthreads();

    if (tid < FP) {
        int f = tid;
        __half* dst = g_xeT + ((size_t)(head * NTA + mt) * FP + f) * BKA;
#pragma unroll
        for (int i = 0; i < 4; i++) {
            __half2 q[4];
#pragma unroll
            for (int j = 0; j < 4; j++)
                q[j] = __floats2half2_rn(tile[i * 8 + j * 2][f],
                                         tile[i * 8 + j * 2 + 1][f]);
            uint4 v = make_uint4(*(u32*)&q[0], *(u32*)&q[1],
                                 *(u32*)&q[2], *(u32*)&q[3]);
            *(uint4*)(dst + i * 8) = v;
        }
    }
}

// ---------------- K4: split-m attention (ldmatrix + shfl-mask) ---------------
__device__ __forceinline__ float elu2(float h) {
    if (h <= 0.f) {
        h = __expf(h) - 1.0f;
        h = __expf(h) - 1.0f;
    }
    return h;
}

__global__ void __launch_bounds__(128, 5) k_attn() {
    int kh = blockIdx.y;
    int n0 = blockIdx.x * TMA;
    int sp = blockIdx.z;
    int mbase = sp * MSPL;
    int tid = threadIdx.x;
    int lane = tid & 31, w = tid >> 5;
    int gid = lane >> 2, tig = lane & 3;
    int row0 = w * 16;

    __shared__ __align__(16) __half s_p[2][TMA][40];
    __shared__ __align__(16) __half s_xt[2][TMA][40];
    __shared__ float s_hl[TMA];

    if (tid < TMA) s_hl[tid] = g_hl[kh * NN + n0 + tid];

    float acc[8][4];
#pragma unroll
    for (int t = 0; t < 8; t++)
#pragma unroll
        for (int q = 0; q < 4; q++) acc[t][q] = 0.f;
    float sumreg[16];
#pragma unroll
    for (int r = 0; r < 16; r++) sumreg[r] = 0.f;

    int xr = tid >> 1;            // f row 0..63
    int xs = (tid & 1) * 16;      // half offset 0/16

    // ldmatrix base addresses (per buffer, lane-dependent parts precomputed)
    // A: rows row0+(lane&15), col block +8 halves (16B) for lanes>=16
    u32 a_off = (u32)(row0 + (lane & 15)) * 80u + ((lane & 16) ? 16u : 0u);
    u32 a_addr0 = smem_u32(&s_p[0][0][0]) + a_off;
    u32 a_addr1 = smem_u32(&s_p[1][0][0]) + a_off;
    // B: matrix j=lane>>3 -> n = j*8 + (lane&7); th adds 32 rows (2560 B)
    u32 b_off = (u32)((lane >> 3) * 8 + (lane & 7)) * 80u;
    u32 b_addr0 = smem_u32(&s_xt[0][0][0]) + b_off;
    u32 b_addr1 = smem_u32(&s_xt[1][0][0]) + b_off;

    __syncthreads();   // s_hl visible

#define STAGE(mb, buf)                                                         \
    do {                                                                       \
        int m0 = mbase + (mb) * BKA;                                           \
        const __half* xsrc = g_xeT +                                           \
            ((size_t)(kh * NTA + (m0 >> 5)) * FP + xr) * BKA + xs;             \
        uint4 xv0 = *(const uint4*)(xsrc);                                     \
        uint4 xv1 = *(const uint4*)(xsrc + 8);                                 \
        *(uint4*)(&s_xt[buf][xr][xs])     = xv0;                               \
        *(uint4*)(&s_xt[buf][xr][xs + 8]) = xv1;                               \
        float hrv = g_hr[kh * NN + m0 + lane];                                 \
        u32 mword = g_mbits[(size_t)(m0 >> 5) * NN + n0 + row0 + (lane & 15)]; \
        _Pragma("unroll")                                                      \
        for (int r = 0; r < 16; r++) {                                         \
            u32 bt = __shfl_sync(0xffffffffu, mword, r);                       \
            float e = s_hl[row0 + r] + hrv;                                    \
            e = fmaxf(e, 0.2f * e);                                            \
            float p = ((bt >> lane) & 1u) ? __expf(e) : 0.0f;                  \
            __half ph = __float2half_rn(p);                                    \
            s_p[buf][row0 + r][lane] = ph;                                     \
            sumreg[r] += __half2float(ph);                                     \
        }                                                                      \
    } while (0)

#define MMA_TILE(A_ADDR, B_ADDR)                                               \
    do {                                                                       \
        _Pragma("unroll")                                                      \
        for (int ks = 0; ks < 2; ks++) {                                       \
            u32 a0, a1, a2, a3;                                                \
            ldsm_x4(a0, a1, a2, a3, (A_ADDR) + ks * 32);                       \
            u32 b0[8], b1[8];                                                  \
            ldsm_x4(b0[0], b0[1], b0[2], b0[3], (B_ADDR) + ks * 32);           \
            ldsm_x4(b0[4], b0[5], b0[6], b0[7], (B_ADDR) + 2560 + ks * 32);    \
            ldsm_x4(b1[0], b1[1], b1[2], b1[3], (B_ADDR) + ks * 32 + 16);      \
            ldsm_x4(b1[4], b1[5], b1[6], b1[7], (B_ADDR) + 2560 + ks * 32 + 16); \
            _Pragma("unroll")                                                  \
            for (int t = 0; t < 8; t++)                                        \
                HMMA(acc[t], a0, a1, a2, a3, b0[t], b1[t]);                    \
        }                                                                      \
    } while (0)

    STAGE(0, 0);

    for (int mb = 0; mb < TPS; mb += 2) {
        __syncthreads();                       // buf0 staged; prior buf1 mma done
        if (mb + 1 < TPS) STAGE(mb + 1, 1);
        MMA_TILE(a_addr0, b_addr0);
        __syncthreads();                       // buf1 staged; buf0 mma done
        if (mb + 2 < TPS) STAGE(mb + 2, 0);
        MMA_TILE(a_addr1, b_addr1);
    }
#undef STAGE
#undef MMA_TILE

    // partial row sums -> global
#pragma unroll
    for (int r = 0; r < 16; r++) {
        float s = sumreg[r];
#pragma unroll
        for (int off = 16; off; off >>= 1)
            s += __shfl_xor_sync(0xffffffffu, s, off);
        if (lane == 0)
            g_ps[(sp * KK + kh) * NN + n0 + row0 + r] = s;
    }

    // partial O (no normalize/elu)
    float* po = g_po + (size_t)sp * NN * KF;
#pragma unroll
    for (int half = 0; half < 2; half++) {
        int row = row0 + gid + half * 8;
#pragma unroll
        for (int t = 0; t < 8; t++) {
            size_t base = (size_t)(n0 + row) * KF + kh * FP + t * 8 + 2 * tig;
            *(float2*)(&po[base]) =
                make_float2(acc[t][2 * half + 0], acc[t][2 * half + 1]);
        }
    }
}

// ---------------- K5: combine splits: out = elu2((sum po)/(sum ps)) ----------
__global__ void __launch_bounds__(256) k_combine(float* __restrict__ out) {
    int n = blockIdx.x;
    int tid = threadIdx.x;
    int k = tid >> 5;
    float z = 0.f;
#pragma unroll
    for (int sp = 0; sp < SPLIT; sp++)
        z += g_ps[(sp * KK + k) * NN + n];
    float inv = 1.0f / z;
    size_t off = (size_t)n * KF + tid * 2;
    float ox = 0.f, oy = 0.f;
#pragma unroll
    for (int sp = 0; sp < SPLIT; sp++) {
        float2 o = *(const float2*)(&g_po[(size_t)sp * NN * KF + off]);
        ox += o.x;
        oy += o.y;
    }
    *(float2*)(&out[off]) = make_float2(elu2(ox * inv), elu2(oy * inv));
}

// ---------------- K6: write mask back as second tuple element ----------------
__global__ void __launch_bounds__(256) k_write_mask(const void* __restrict__ mask,
                                                    float* __restrict__ out,
                                                    long extra) {
    int code = detect_code_block(mask);
    long stride = (long)gridDim.x * blockDim.x;
    for (long i = (long)blockIdx.x * blockDim.x + threadIdx.x; i < extra; i += stride) {
        float v = 0.f;
        if (i < (long)NN * NN) v = mask_at(mask, code, (size_t)i) ? 1.f : 0.f;
        out[(long)NN * KF + i] = v;
    }
}

// ---------------- launch ----------------
extern "C" void kernel_launch(void* const* d_in, const int* in_sizes, int n_in,
                              void* d_out, int out_size) {
    const float* x  = (const float*)d_in[0];
    const float* W  = (const float*)d_in[1];
    const float* b  = (const float*)d_in[2];
    const float* aL = (const float*)d_in[3];
    const float* aR = (const float*)d_in[4];
    const void*  mk = d_in[5];
    float* out = (float*)d_out;

    k_bitpack<<<NN * (NN / 32) / 256, 256>>>(mk);        // 1

    dim3 g1(KK, NN / 64);
    gemm_xe<<<g1, 256>>>(x, W, b, aL, aR);               // 2

    dim3 g2(NTA, KK);
    k_xt<<<g2, 128>>>();                                 // 3

    dim3 g3(NN / TMA, KK, SPLIT);                        // (64, 8, 4) = 2048 CTAs
    k_attn<<<g3, 128>>>();                               // 4  <- ncu capture slot

    k_combine<<<NN, 256>>>(out);                         // 5

    long extra = (long)out_size - (long)NN * KF;
    if (extra > 0)
        k_write_mask<<<1024, 256>>>(mk, out, extra);     // 6
}

// round 16
// speedup vs baseline: 1.2375x; 1.2375x over previous
#include <cuda_runtime.h>
#include <cuda_fp16.h>
#include <cstddef>
#include <cstdint>

#define NN 4096
#define FF 256
#define KK 8
#define FP 64
#define KF 512   // KK*FP

#define BKA 32
#define NTA (NN / BKA)        // 128 m-tiles total
#define TMA 64                // n-rows per CTA
#define SPLIT 4
#define MSPL (NN / SPLIT)     // 1024 m per split
#define TPS (MSPL / BKA)      // 32 tiles per CTA

typedef unsigned int u32;

// ---------------- scratch (static device globals; no allocation) ----------------
__device__ float  g_xe[NN * KF];              // 8 MB xe[n][k*64+f]
__device__ __half g_xeT[KK * NTA * FP * BKA]; // 4 MB tiled: [k][mtile][f][32]
__device__ float2 g_ehl2[KK * NN];            // (exp(hl), exp(0.2*hl))
__device__ float2 g_ehr2[KK * NN];            // (exp(hr), exp(0.2*hr))
__device__ u32    g_mbits[NTA * NN];          // 2 MB bit-packed mask, TRANSPOSED [mw][n]
__device__ float  g_po[SPLIT * NN * KF];      // 32 MB partial O
__device__ float  g_ps[SPLIT * KK * NN];      // partial row sums
__device__ int    g_code;                     // 0=u8/bool, 1=int32, 2=float32

// ---------------- mask accessor ----------------
__device__ __forceinline__ unsigned mask_at(const void* m, int code, size_t idx) {
    if (code == 0)      return (unsigned)((const unsigned char*)m)[idx];
    else if (code == 1) return ((const int*)m)[idx] != 0;
    else                return __float_as_uint(((const float*)m)[idx]) != 0u;
}

// per-block dtype detection on first 4 KB (deterministic; all blocks agree)
__device__ __forceinline__ int detect_code_block(const void* mask) {
    __shared__ u32 sh0, sh1;
    if (threadIdx.x == 0) { sh0 = 0u; sh1 = 0u; }
    __syncthreads();
    const u32* wp = (const u32*)mask;
    u32 o0 = 0u, o1 = 0u;
    for (int i = threadIdx.x; i < 1024; i += blockDim.x) {
        u32 v = wp[i];
        o0 |= (v & 0xFFu);
        o1 |= ((v >> 8) & 0xFFu);
    }
    atomicOr(&sh0, o0);
    atomicOr(&sh1, o1);
    __syncthreads();
    return sh1 ? 0 : (sh0 ? 1 : 2);
}

__device__ __forceinline__ u32 smem_u32(const void* p) {
    u32 a;
    asm("{ .reg .u64 t; cvta.to.shared.u64 t, %1; cvt.u32.u64 %0, t; }"
        : "=r"(a) : "l"(p));
    return a;
}

__device__ __forceinline__ void ldsm_x4(u32& r0, u32& r1, u32& r2, u32& r3, u32 a) {
    asm volatile("ldmatrix.sync.aligned.m8n8.x4.shared.b16 {%0,%1,%2,%3}, [%4];"
                 : "=r"(r0), "=r"(r1), "=r"(r2), "=r"(r3) : "r"(a));
}

#define HMMA(ac, a0, a1, a2, a3, bb0, bb1)                                     \
    asm("mma.sync.aligned.m16n8k16.row.col.f32.f16.f16.f32 "                   \
        "{%0,%1,%2,%3}, {%4,%5,%6,%7}, {%8,%9}, {%0,%1,%2,%3};"                \
        : "+f"((ac)[0]), "+f"((ac)[1]), "+f"((ac)[2]), "+f"((ac)[3])           \
        : "r"(a0), "r"(a1), "r"(a2), "r"(a3), "r"(bb0), "r"(bb1))

// ---------------- K1: bit-pack mask, TRANSPOSED [mw][n] ----------------
__global__ void __launch_bounds__(256) k_bitpack(const void* __restrict__ mask) {
    int code = detect_code_block(mask);
    if (blockIdx.x == 0 && threadIdx.x == 0) g_code = code;
    int idx = blockIdx.x * blockDim.x + threadIdx.x;   // 0 .. NN*128-1
    int n = idx >> 7, mw = idx & 127;
    u32 bits = 0u;
    if (code == 0) {
        const u32* wp = (const u32*)mask + (size_t)idx * 8;
#pragma unroll
        for (int i = 0; i < 8; i++) {
            u32 v = wp[i];
            bits |= ((v & 1u) << (4 * i)) | (((v >> 8) & 1u) << (4 * i + 1)) |
                    (((v >> 16) & 1u) << (4 * i + 2)) | (((v >> 24) & 1u) << (4 * i + 3));
        }
    } else {
        size_t base = (size_t)idx * 32;
        for (int j = 0; j < 32; j++)
            bits |= mask_at(mask, code, base + j) << j;
    }
    g_mbits[(size_t)mw * NN + n] = bits;
}

// ---------------- K2: xe = x @ W^T + b, fused hl/hr -> exp factors ----------
__global__ void __launch_bounds__(256) gemm_xe(const float* __restrict__ x,
                                               const float* __restrict__ W,
                                               const float* __restrict__ b,
                                               const float* __restrict__ aL,
                                               const float* __restrict__ aR) {
    __shared__ float sA[16][68];
    __shared__ float sB[16][68];
    int tid = threadIdx.x;
    int tx = tid & 15, ty = tid >> 4;
    int row0 = blockIdx.y * 64;
    int head = blockIdx.x;
    int col0 = head * 64;
    float acc[4][4];
#pragma unroll
    for (int i = 0; i < 4; i++)
#pragma unroll
        for (int j = 0; j < 4; j++) acc[i][j] = 0.f;

    for (int t = 0; t < FF / 16; t++) {
#pragma unroll
        for (int l = 0; l < 4; l++) {
            int idx = tid + l * 256;
            int mm = idx >> 4, kk = idx & 15;
            sA[kk][mm] = x[(size_t)(row0 + mm) * FF + t * 16 + kk];
            sB[kk][mm] = W[(size_t)(col0 + mm) * FF + t * 16 + kk];
        }
        __syncthreads();
#pragma unroll
        for (int kk = 0; kk < 16; kk++) {
            float a[4], bv[4];
#pragma unroll
            for (int i = 0; i < 4; i++) a[i] = sA[kk][ty * 4 + i];
#pragma unroll
            for (int j = 0; j < 4; j++) bv[j] = sB[kk][tx * 4 + j];
#pragma unroll
            for (int i = 0; i < 4; i++)
#pragma unroll
                for (int j = 0; j < 4; j++) acc[i][j] += a[i] * bv[j];
        }
        __syncthreads();
    }

    float hlv[4] = {0.f, 0.f, 0.f, 0.f}, hrv[4] = {0.f, 0.f, 0.f, 0.f};
#pragma unroll
    for (int j = 0; j < 4; j++) {
        int c = col0 + tx * 4 + j;
        float aLj = aL[head * FP + tx * 4 + j];
        float aRj = aR[head * FP + tx * 4 + j];
        float bj = b[c];
#pragma unroll
        for (int i = 0; i < 4; i++) {
            float v = acc[i][j] + bj;
            hlv[i] += v * aLj;
            hrv[i] += v * aRj;
            g_xe[(size_t)(row0 + ty * 4 + i) * KF + c] = v;
        }
    }
#pragma unroll
    for (int i = 0; i < 4; i++) {
#pragma unroll
        for (int off = 8; off; off >>= 1) {
            hlv[i] += __shfl_xor_sync(0xffffffffu, hlv[i], off);
            hrv[i] += __shfl_xor_sync(0xffffffffu, hrv[i], off);
        }
    }
    if (tx == 0) {
#pragma unroll
        for (int i = 0; i < 4; i++) {
            int n = row0 + ty * 4 + i;
            g_ehl2[head * NN + n] = make_float2(__expf(hlv[i]), __expf(0.2f * hlv[i]));
            g_ehr2[head * NN + n] = make_float2(__expf(hrv[i]), __expf(0.2f * hrv[i]));
        }
    }
}

// ---------------- K3: xe -> TILED fp16 xeT[k][mtile][f][32] ------------------
__global__ void __launch_bounds__(128) k_xt() {
    __shared__ float tile[32][65];
    int tid = threadIdx.x;
    int mt = blockIdx.x, head = blockIdx.y;

    int r = tid >> 2, c = (tid & 3) * 16;
    const float* src = &g_xe[(size_t)(mt * 32 + r) * KF + head * FP + c];
#pragma unroll
    for (int i = 0; i < 4; i++) {
        float4 v = *(const float4*)(src + i * 4);
        tile[r][c + i * 4 + 0] = v.x;
        tile[r][c + i * 4 + 1] = v.y;
        tile[r][c + i * 4 + 2] = v.z;
        tile[r][c + i * 4 + 3] = v.w;
    }
    __syncthreads();

    if (tid < FP) {
        int f = tid;
        __half* dst = g_xeT + ((size_t)(head * NTA + mt) * FP + f) * BKA;
#pragma unroll
        for (int i = 0; i < 4; i++) {
            __half2 q[4];
#pragma unroll
            for (int j = 0; j < 4; j++)
                q[j] = __floats2half2_rn(tile[i * 8 + j * 2][f],
                                         tile[i * 8 + j * 2 + 1][f]);
            uint4 v = make_uint4(*(u32*)&q[0], *(u32*)&q[1],
                                 *(u32*)&q[2], *(u32*)&q[3]);
            *(uint4*)(dst + i * 8) = v;
        }
    }
}

// ---------------- K4: split-m attention (prefetched, exp-free inner loop) ----
__device__ __forceinline__ float elu2(float h) {
    if (h <= 0.f) {
        h = __expf(h) - 1.0f;
        h = __expf(h) - 1.0f;
    }
    return h;
}

__global__ void __launch_bounds__(128, 5) k_attn() {
    int kh = blockIdx.y;
    int n0 = blockIdx.x * TMA;
    int sp = blockIdx.z;
    int mbase = sp * MSPL;
    int tid = threadIdx.x;
    int lane = tid & 31, w = tid >> 5;
    int gid = lane >> 2, tig = lane & 3;
    int row0 = w * 16;

    __shared__ __align__(16) __half s_p[2][TMA][40];
    __shared__ __align__(16) __half s_xt[2][TMA][40];
    __shared__ float2 s_ep[TMA];       // (exp(hl), exp(0.2 hl)) per row

    if (tid < TMA) s_ep[tid] = g_ehl2[kh * NN + n0 + tid];

    float acc[8][4];
#pragma unroll
    for (int t = 0; t < 8; t++)
#pragma unroll
        for (int q = 0; q < 4; q++) acc[t][q] = 0.f;
    float sumreg[16];
#pragma unroll
    for (int r = 0; r < 16; r++) sumreg[r] = 0.f;

    int xr = tid >> 1;            // f row 0..63
    int xs = (tid & 1) * 16;      // half offset 0/16

    // ldmatrix base addresses
    u32 a_off = (u32)(row0 + (lane & 15)) * 80u + ((lane & 16) ? 16u : 0u);
    u32 a_addr0 = smem_u32(&s_p[0][0][0]) + a_off;
    u32 a_addr1 = smem_u32(&s_p[1][0][0]) + a_off;
    u32 b_off = (u32)((lane >> 3) * 8 + (lane & 7)) * 80u;
    u32 b_addr0 = smem_u32(&s_xt[0][0][0]) + b_off;
    u32 b_addr1 = smem_u32(&s_xt[1][0][0]) + b_off;

    __syncthreads();   // s_ep visible

    // prefetch registers (tile data in flight)
    uint4 pfx0, pfx1;
    float2 pfe;
    u32 pfm;

#define PREFETCH(mb)                                                           \
    do {                                                                       \
        int m0 = mbase + (mb) * BKA;                                           \
        const __half* xsrc = g_xeT +                                           \
            ((size_t)(kh * NTA + (m0 >> 5)) * FP + xr) * BKA + xs;             \
        pfx0 = *(const uint4*)(xsrc);                                          \
        pfx1 = *(const uint4*)(xsrc + 8);                                      \
        pfe  = g_ehr2[kh * NN + m0 + lane];                                    \
        pfm  = g_mbits[(size_t)(m0 >> 5) * NN + n0 + row0 + (lane & 15)];      \
    } while (0)

#define PRODUCE(buf)                                                           \
    do {                                                                       \
        *(uint4*)(&s_xt[buf][xr][xs])     = pfx0;                              \
        *(uint4*)(&s_xt[buf][xr][xs + 8]) = pfx1;                              \
        _Pragma("unroll")                                                      \
        for (int r = 0; r < 16; r++) {                                         \
            u32 bt = __shfl_sync(0xffffffffu, pfm, r);                         \
            float2 ep = s_ep[row0 + r];                                        \
            float p = fmaxf(ep.x * pfe.x, ep.y * pfe.y);                       \
            p = ((bt >> lane) & 1u) ? p : 0.f;                                 \
            __half ph = __float2half_rn(p);                                    \
            s_p[buf][row0 + r][lane] = ph;                                     \
            sumreg[r] += __half2float(ph);                                     \
        }                                                                      \
    } while (0)

#define MMA_TILE(A_ADDR, B_ADDR)                                               \
    do {                                                                       \
        _Pragma("unroll")                                                      \
        for (int ks = 0; ks < 2; ks++) {                                       \
            u32 a0, a1, a2, a3;                                                \
            ldsm_x4(a0, a1, a2, a3, (A_ADDR) + ks * 32);                       \
            u32 b0[8], b1[8];                                                  \
            ldsm_x4(b0[0], b0[1], b0[2], b0[3], (B_ADDR) + ks * 32);           \
            ldsm_x4(b0[4], b0[5], b0[6], b0[7], (B_ADDR) + 2560 + ks * 32);    \
            ldsm_x4(b1[0], b1[1], b1[2], b1[3], (B_ADDR) + ks * 32 + 16);      \
            ldsm_x4(b1[4], b1[5], b1[6], b1[7], (B_ADDR) + 2560 + ks * 32 + 16); \
            _Pragma("unroll")                                                  \
            for (int t = 0; t < 8; t++)                                        \
                HMMA(acc[t], a0, a1, a2, a3, b0[t], b1[t]);                    \
        }                                                                      \
    } while (0)

    PREFETCH(0);

    for (int mb = 0; mb < TPS; mb++) {
        int cur = mb & 1;
        PRODUCE(cur);                          // consume prefetched regs
        if (mb + 1 < TPS) PREFETCH(mb + 1);    // issue LDGs; hidden by sync+mma
        __syncthreads();                       // cur staged by all warps
        MMA_TILE(cur ? a_addr1 : a_addr0, cur ? b_addr1 : b_addr0);
    }
#undef PREFETCH
#undef PRODUCE
#undef MMA_TILE

    // partial row sums -> global
#pragma unroll
    for (int r = 0; r < 16; r++) {
        float s = sumreg[r];
#pragma unroll
        for (int off = 16; off; off >>= 1)
            s += __shfl_xor_sync(0xffffffffu, s, off);
        if (lane == 0)
            g_ps[(sp * KK + kh) * NN + n0 + row0 + r] = s;
    }

    // partial O (no normalize/elu)
    float* po = g_po + (size_t)sp * NN * KF;
#pragma unroll
    for (int half = 0; half < 2; half++) {
        int row = row0 + gid + half * 8;
#pragma unroll
        for (int t = 0; t < 8; t++) {
            size_t base = (size_t)(n0 + row) * KF + kh * FP + t * 8 + 2 * tig;
            *(float2*)(&po[base]) =
                make_float2(acc[t][2 * half + 0], acc[t][2 * half + 1]);
        }
    }
}

// ---------------- K5: combine splits: out = elu2((sum po)/(sum ps)) ----------
__global__ void __launch_bounds__(256) k_combine(float* __restrict__ out) {
    int n = blockIdx.x;
    int tid = threadIdx.x;
    int k = tid >> 5;
    float z = 0.f;
#pragma unroll
    for (int sp = 0; sp < SPLIT; sp++)
        z += g_ps[(sp * KK + k) * NN + n];
    float inv = 1.0f / z;
    size_t off = (size_t)n * KF + tid * 2;
    float ox = 0.f, oy = 0.f;
#pragma unroll
    for (int sp = 0; sp < SPLIT; sp++) {
        float2 o = *(const float2*)(&g_po[(size_t)sp * NN * KF + off]);
        ox += o.x;
        oy += o.y;
    }
    *(float2*)(&out[off]) = make_float2(elu2(ox * inv), elu2(oy * inv));
}

// ---------------- K6: write mask back as second tuple element ----------------
__global__ void __launch_bounds__(256) k_write_mask(const void* __restrict__ mask,
                                                    float* __restrict__ out,
                                                    long extra) {
    int code = detect_code_block(mask);
    long stride = (long)gridDim.x * blockDim.x;
    for (long i = (long)blockIdx.x * blockDim.x + threadIdx.x; i < extra; i += stride) {
        float v = 0.f;
        if (i < (long)NN * NN) v = mask_at(mask, code, (size_t)i) ? 1.f : 0.f;
        out[(long)NN * KF + i] = v;
    }
}

// ---------------- launch ----------------
extern "C" void kernel_launch(void* const* d_in, const int* in_sizes, int n_in,
                              void* d_out, int out_size) {
    const float* x  = (const float*)d_in[0];
    const float* W  = (const float*)d_in[1];
    const float* b  = (const float*)d_in[2];
    const float* aL = (const float*)d_in[3];
    const float* aR = (const float*)d_in[4];
    const void*  mk = d_in[5];
    float* out = (float*)d_out;

    k_bitpack<<<NN * (NN / 32) / 256, 256>>>(mk);        // 1

    dim3 g1(KK, NN / 64);
    gemm_xe<<<g1, 256>>>(x, W, b, aL, aR);               // 2

    dim3 g2(NTA, KK);
    k_xt<<<g2, 128>>>();                                 // 3

    dim3 g3(NN / TMA, KK, SPLIT);                        // (64, 8, 4) = 2048 CTAs
    k_attn<<<g3, 128>>>();                               // 4  <- ncu capture slot

    k_combine<<<NN, 256>>>(out);                         // 5

    long extra = (long)out_size - (long)NN * KF;
    if (extra > 0)
        k_write_mask<<<1024, 256>>>(mk, out, extra);     // 6
}